// round 1
// baseline (speedup 1.0000x reference)
#include <cuda_runtime.h>
#include <math_constants.h>

#define BB 2
#define HH 8
#define LL 2048
#define DD 64
#define CC 512
#define NQ 16
#define NK 32
#define BLKQ 128
#define BLKK 64

// ---------------- scratch (no allocations allowed) ----------------
__device__ float g_q[BB*HH*LL*DD];
__device__ float g_k[BB*HH*LL*DD];
__device__ float g_v[BB*HH*LL*DD];
__device__ float g_qm[BB*HH*NQ*DD];
__device__ float g_km[BB*HH*NK*DD];
__device__ float g_qsim[BB*HH*NQ];
__device__ float g_ksim[BB*HH*NK];
__device__ int   g_mask[BB*HH*NQ*NK];
__device__ float g_ot[BB*LL*CC];

// ---------------- QKV GEMM: x[4096,512] @ Wqkv[512,1536] + b, scatter to q/k/v [B,H,L,D] ----------------
__global__ void __launch_bounds__(256) gemm_qkv(const float* __restrict__ A,
                                                const float* __restrict__ W,
                                                const float* __restrict__ bias) {
    __shared__ float As[16][65];
    __shared__ float Bs[16][64];
    const int K = CC, N = 3 * CC;
    int tid = threadIdx.x;
    int tx = tid & 15, ty = tid >> 4;
    int m0 = blockIdx.y * 64, n0 = blockIdx.x * 64;
    float acc[4][4] = {};
    for (int k0 = 0; k0 < K; k0 += 16) {
        #pragma unroll
        for (int i = 0; i < 4; i++) {
            int idx = tid + i * 256;
            int mm = idx >> 4, kk = idx & 15;
            As[kk][mm] = A[(m0 + mm) * K + k0 + kk];
        }
        #pragma unroll
        for (int i = 0; i < 4; i++) {
            int idx = tid + i * 256;
            int kk = idx >> 6, nn = idx & 63;
            Bs[kk][nn] = W[(k0 + kk) * N + n0 + nn];
        }
        __syncthreads();
        #pragma unroll
        for (int kk = 0; kk < 16; kk++) {
            float a0 = As[kk][ty * 4 + 0];
            float a1 = As[kk][ty * 4 + 1];
            float a2 = As[kk][ty * 4 + 2];
            float a3 = As[kk][ty * 4 + 3];
            float4 bv = *(const float4*)&Bs[kk][tx * 4];
            acc[0][0] += a0 * bv.x; acc[0][1] += a0 * bv.y; acc[0][2] += a0 * bv.z; acc[0][3] += a0 * bv.w;
            acc[1][0] += a1 * bv.x; acc[1][1] += a1 * bv.y; acc[1][2] += a1 * bv.z; acc[1][3] += a1 * bv.w;
            acc[2][0] += a2 * bv.x; acc[2][1] += a2 * bv.y; acc[2][2] += a2 * bv.z; acc[2][3] += a2 * bv.w;
            acc[3][0] += a3 * bv.x; acc[3][1] += a3 * bv.y; acc[3][2] += a3 * bv.z; acc[3][3] += a3 * bv.w;
        }
        __syncthreads();
    }
    #pragma unroll
    for (int r = 0; r < 4; r++) {
        int m = m0 + ty * 4 + r;
        int b = m >> 11, l = m & 2047;
        #pragma unroll
        for (int c = 0; c < 4; c++) {
            int j = n0 + tx * 4 + c;
            float val = acc[r][c] + bias[j];
            int t = j >> 9;
            int h = (j >> 6) & 7;
            int d = j & 63;
            float* dst = (t == 0) ? g_q : (t == 1) ? g_k : g_v;
            dst[(((b * HH + h) * LL) + l) * DD + d] = val;
        }
    }
}

// ---------------- block means + min-cosine ----------------
template<int BLK, bool ISQ>
__global__ void __launch_bounds__(128) block_meta(int nb) {
    __shared__ float tile[BLK * 65];
    __shared__ float mean[64];
    __shared__ float red[128];
    __shared__ float nm_s;
    const float* t = ISQ ? g_q : g_k;
    float* mout = ISQ ? g_qm : g_km;
    float* simout = ISQ ? g_qsim : g_ksim;
    int blkid = blockIdx.x % nb;
    int bh = blockIdx.x / nb;
    const float* base = t + (bh * LL + blkid * BLK) * DD;
    int tid = threadIdx.x;
    for (int i = tid; i < BLK * DD; i += 128) {
        int r = i >> 6, d = i & 63;
        tile[r * 65 + d] = base[i];
    }
    __syncthreads();
    if (tid < 64) {
        float s = 0.f;
        for (int r = 0; r < BLK; r++) s += tile[r * 65 + tid];
        s *= (1.0f / BLK);
        mean[tid] = s;
        mout[blockIdx.x * 64 + tid] = s;
    }
    __syncthreads();
    if (tid == 0) {
        float s = 0.f;
        for (int d = 0; d < 64; d++) s += mean[d] * mean[d];
        nm_s = sqrtf(s) + 1e-6f;
    }
    __syncthreads();
    float mycos = CUDART_INF_F;
    if (tid < BLK) {
        float dot = 0.f, nr = 0.f;
        for (int d = 0; d < 64; d++) {
            float xv = tile[tid * 65 + d];
            dot += xv * mean[d];
            nr += xv * xv;
        }
        mycos = dot / ((sqrtf(nr) + 1e-6f) * nm_s);
    }
    red[tid] = mycos;
    __syncthreads();
    for (int s = 64; s > 0; s >>= 1) {
        if (tid < s) red[tid] = fminf(red[tid], red[tid + s]);
        __syncthreads();
    }
    if (tid == 0) simout[blockIdx.x] = red[0];
}

// ---------------- pooled softmax + CDF keep mask ----------------
__global__ void __launch_bounds__(256) mask_kernel() {
    int t = threadIdx.x;             // 0..255 -> (bh, qi)
    int bh = t >> 4, qi = t & 15;
    const float* qmv = g_qm + (bh * NQ + qi) * DD;
    float val[NK];
    int idx[NK];
    float mx = -CUDART_INF_F;
    for (int j = 0; j < NK; j++) {
        const float* kmv = g_km + (bh * NK + j) * DD;
        float dot = 0.f;
        for (int d = 0; d < DD; d++) dot += qmv[d] * kmv[d];
        dot *= 0.125f;
        val[j] = dot; idx[j] = j;
        mx = fmaxf(mx, dot);
    }
    float sum = 0.f;
    for (int j = 0; j < NK; j++) { val[j] = expf(val[j] - mx); sum += val[j]; }
    float invs = 1.0f / sum;
    for (int j = 0; j < NK; j++) val[j] *= invs;
    // stable insertion sort, descending (ties keep original index order)
    for (int i = 1; i < NK; i++) {
        float v = val[i]; int ix = idx[i];
        int jj = i - 1;
        while (jj >= 0 && val[jj] < v) {
            val[jj + 1] = val[jj]; idx[jj + 1] = idx[jj]; jj--;
        }
        val[jj + 1] = v; idx[jj + 1] = ix;
    }
    int keep[NK];
    float prefix = 0.f;
    for (int r = 0; r < NK; r++) {
        keep[idx[r]] = (prefix < 0.98f) ? 1 : 0;
        prefix += val[r];
    }
    int qself = g_qsim[bh * NQ + qi] > 0.6f;
    for (int j = 0; j < NK; j++) {
        int kself = g_ksim[bh * NK + j] > 0.6f;
        g_mask[(bh * NQ + qi) * NK + j] = keep[j] | (!qself) | (!kself);
    }
}

// ---------------- masked flash attention, per-key online softmax ----------------
__global__ void __launch_bounds__(128) attn_kernel() {
    __shared__ float Ks[64 * 64];
    __shared__ float Vs[64 * 64];
    int bh = blockIdx.y;     // 0..15
    int qb = blockIdx.x;     // 0..15
    int tid = threadIdx.x;   // 0..127
    int row = qb * BLKQ + tid;
    const float* qp = g_q + (bh * LL + row) * DD;
    float qreg[64];
    #pragma unroll
    for (int i = 0; i < 16; i++) {
        float4 v = *(const float4*)(qp + i * 4);
        qreg[i * 4 + 0] = v.x; qreg[i * 4 + 1] = v.y;
        qreg[i * 4 + 2] = v.z; qreg[i * 4 + 3] = v.w;
    }
    float m = -CUDART_INF_F, l = 0.f;
    float acc[64];
    #pragma unroll
    for (int d = 0; d < 64; d++) acc[d] = 0.f;
    const int* maskrow = g_mask + (bh * NQ + qb) * NK;

    for (int kb = 0; kb < NK; kb++) {
        if (!maskrow[kb]) continue;   // uniform across block
        __syncthreads();
        const float4* Kg = (const float4*)(g_k + (bh * LL + kb * BLKK) * DD);
        const float4* Vg = (const float4*)(g_v + (bh * LL + kb * BLKK) * DD);
        #pragma unroll
        for (int i = 0; i < 8; i++) {
            int idx = tid + i * 128;
            ((float4*)Ks)[idx] = Kg[idx];
            ((float4*)Vs)[idx] = Vg[idx];
        }
        __syncthreads();
        #pragma unroll 2
        for (int j = 0; j < 64; j++) {
            float s = 0.f;
            #pragma unroll
            for (int i = 0; i < 16; i++) {
                float4 kv = *(const float4*)&Ks[j * 64 + i * 4];
                s += qreg[i * 4 + 0] * kv.x + qreg[i * 4 + 1] * kv.y
                   + qreg[i * 4 + 2] * kv.z + qreg[i * 4 + 3] * kv.w;
            }
            s *= 0.125f;
            float p;
            if (s > m) {
                float f = __expf(m - s);
                l *= f;
                #pragma unroll
                for (int d = 0; d < 64; d++) acc[d] *= f;
                m = s;
                p = 1.0f;
            } else {
                p = __expf(s - m);
            }
            l += p;
            #pragma unroll
            for (int i = 0; i < 16; i++) {
                float4 vv = *(const float4*)&Vs[j * 64 + i * 4];
                acc[i * 4 + 0] += p * vv.x; acc[i * 4 + 1] += p * vv.y;
                acc[i * 4 + 2] += p * vv.z; acc[i * 4 + 3] += p * vv.w;
            }
        }
    }
    int b = bh >> 3, h = bh & 7;
    float inv = 1.0f / l;
    float* op = g_ot + (b * LL + row) * CC + h * DD;
    #pragma unroll
    for (int i = 0; i < 16; i++) {
        float4 v;
        v.x = acc[i * 4 + 0] * inv; v.y = acc[i * 4 + 1] * inv;
        v.z = acc[i * 4 + 2] * inv; v.w = acc[i * 4 + 3] * inv;
        *(float4*)(op + i * 4) = v;
    }
}

// ---------------- output projection: ot[4096,512] @ Wproj[512,512] + b ----------------
__global__ void __launch_bounds__(256) gemm_proj(const float* __restrict__ W,
                                                 const float* __restrict__ bias,
                                                 float* __restrict__ out) {
    __shared__ float As[16][65];
    __shared__ float Bs[16][64];
    const int K = CC, N = CC;
    const float* A = g_ot;
    int tid = threadIdx.x;
    int tx = tid & 15, ty = tid >> 4;
    int m0 = blockIdx.y * 64, n0 = blockIdx.x * 64;
    float acc[4][4] = {};
    for (int k0 = 0; k0 < K; k0 += 16) {
        #pragma unroll
        for (int i = 0; i < 4; i++) {
            int idx = tid + i * 256;
            int mm = idx >> 4, kk = idx & 15;
            As[kk][mm] = A[(m0 + mm) * K + k0 + kk];
        }
        #pragma unroll
        for (int i = 0; i < 4; i++) {
            int idx = tid + i * 256;
            int kk = idx >> 6, nn = idx & 63;
            Bs[kk][nn] = W[(k0 + kk) * N + n0 + nn];
        }
        __syncthreads();
        #pragma unroll
        for (int kk = 0; kk < 16; kk++) {
            float a0 = As[kk][ty * 4 + 0];
            float a1 = As[kk][ty * 4 + 1];
            float a2 = As[kk][ty * 4 + 2];
            float a3 = As[kk][ty * 4 + 3];
            float4 bv = *(const float4*)&Bs[kk][tx * 4];
            acc[0][0] += a0 * bv.x; acc[0][1] += a0 * bv.y; acc[0][2] += a0 * bv.z; acc[0][3] += a0 * bv.w;
            acc[1][0] += a1 * bv.x; acc[1][1] += a1 * bv.y; acc[1][2] += a1 * bv.z; acc[1][3] += a1 * bv.w;
            acc[2][0] += a2 * bv.x; acc[2][1] += a2 * bv.y; acc[2][2] += a2 * bv.z; acc[2][3] += a2 * bv.w;
            acc[3][0] += a3 * bv.x; acc[3][1] += a3 * bv.y; acc[3][2] += a3 * bv.z; acc[3][3] += a3 * bv.w;
        }
        __syncthreads();
    }
    #pragma unroll
    for (int r = 0; r < 4; r++) {
        int m = m0 + ty * 4 + r;
        #pragma unroll
        for (int c = 0; c < 4; c++) {
            int j = n0 + tx * 4 + c;
            out[m * N + j] = acc[r][c] + bias[j];
        }
    }
}

extern "C" void kernel_launch(void* const* d_in, const int* in_sizes, int n_in,
                              void* d_out, int out_size) {
    const float* x     = (const float*)d_in[0];
    const float* Wqkv  = (const float*)d_in[1];
    const float* bqkv  = (const float*)d_in[2];
    const float* Wproj = (const float*)d_in[3];
    const float* bproj = (const float*)d_in[4];
    float* out = (float*)d_out;

    dim3 g1(24, 64);                       // N=1536/64, M=4096/64
    gemm_qkv<<<g1, 256>>>(x, Wqkv, bqkv);

    block_meta<BLKQ, true><<<BB * HH * NQ, 128>>>(NQ);
    block_meta<BLKK, false><<<BB * HH * NK, 128>>>(NK);

    mask_kernel<<<1, 256>>>();

    dim3 ga(NQ, BB * HH);
    attn_kernel<<<ga, 128>>>();

    dim3 g2(8, 64);                        // N=512/64, M=4096/64
    gemm_proj<<<g2, 256>>>(Wproj, bproj, out);
}